// round 15
// baseline (speedup 1.0000x reference)
#include <cuda_runtime.h>
#include <cuda_bf16.h>
#include <cstdint>

#define N_NODES 100000
#define N_EDGES 1600000
#define DIM     128
#define T_NODES 4096
#define P_PAIRS 131072
#define HP      256
#define DOUT    128
#define ZDIM    64

// ---------------- scratch (static device globals; no allocation) ----------------
__device__ int   g_cnt[N_NODES];
__device__ int   g_rowptr[N_NODES + 1];
__device__ int   g_cursor[N_NODES];
__device__ int   g_col[N_EDGES];
__device__ float g_invdeg[N_NODES];
__device__ unsigned char g_flag[N_NODES];
__device__ unsigned char g_tflag[N_NODES];
__device__ float g_pe[N_NODES * 4];
__device__ float g_zb[HP];
// stage-1 predictor weights, chunk-major tf32: chunks 0..3: [n(256)][kk(32)] each 8192;
// chunk 4 (Wp1 rows 192..199): [n(256)][kk(8)] = 2048 at offset 4*8192.
__device__ unsigned g_wt1[4 * 8192 + 2048];
// stage-2 weights (Wp2), chunk-major tf32: 8 chunks of [n(128)][kk(32)] = 4096 each.
__device__ unsigned g_wt2[8 * 4096];
__device__ float g_buf1[(size_t)N_NODES * DIM];    // gemm_t out (bf16) -> later m (fp32)
__device__ float g_buf2[(size_t)N_NODES * DIM];    // gemm_c out (bf16)
__device__ float g_buf3[(size_t)N_NODES * DIM];    // ht (fp32, tflag rows)
__device__ float g_buf4[(size_t)N_NODES * DIM];    // h_c (bf16)
__device__ float g_tbuf[(size_t)T_NODES * DIM];

// ---------------- tf32 / mma / bf16 helpers ----------------
__device__ __forceinline__ unsigned f2tf(float f) {
    unsigned u;
    asm("cvt.rna.tf32.f32 %0, %1;" : "=r"(u) : "f"(f));
    return u;
}
__device__ __forceinline__ void mma8(float* c, const unsigned* a, const unsigned* b) {
    asm volatile(
        "mma.sync.aligned.m16n8k8.row.col.f32.tf32.tf32.f32 "
        "{%0,%1,%2,%3},{%4,%5,%6,%7},{%8,%9},{%0,%1,%2,%3};"
        : "+f"(c[0]), "+f"(c[1]), "+f"(c[2]), "+f"(c[3])
        : "r"(a[0]), "r"(a[1]), "r"(a[2]), "r"(a[3]), "r"(b[0]), "r"(b[1]));
}
__device__ __forceinline__ void ldsm4(unsigned* r, const unsigned* p) {
    unsigned addr = (unsigned)__cvta_generic_to_shared(p);
    asm volatile("ldmatrix.sync.aligned.m8n8.x4.shared.b16 {%0,%1,%2,%3}, [%4];"
                 : "=r"(r[0]), "=r"(r[1]), "=r"(r[2]), "=r"(r[3]) : "r"(addr));
}
__device__ __forceinline__ float4 bf4_load(const __nv_bfloat16* p) {
    uint2 u = *(const uint2*)p;
    __nv_bfloat162 a = *reinterpret_cast<const __nv_bfloat162*>(&u.x);
    __nv_bfloat162 b = *reinterpret_cast<const __nv_bfloat162*>(&u.y);
    float2 fa = __bfloat1622float2(a), fb = __bfloat1622float2(b);
    return make_float4(fa.x, fa.y, fb.x, fb.y);
}
__device__ __forceinline__ void bf4_store(__nv_bfloat16* p, float4 v) {
    __nv_bfloat162 a = __float22bfloat162_rn(make_float2(v.x, v.y));
    __nv_bfloat162 b = __float22bfloat162_rn(make_float2(v.z, v.w));
    uint2 u;
    u.x = *reinterpret_cast<unsigned*>(&a);
    u.y = *reinterpret_cast<unsigned*>(&b);
    *(uint2*)p = u;
}

// ---------------- GEMM body (R10-proven, ldmatrix) ----------------
#define AS_STR 36
#define BT_STR 36
#define GM 782   // gemm grid for M = N_NODES

__device__ void gemm_body(int bid, const float* __restrict__ A,
                          const float* __restrict__ B, float* __restrict__ C,
                          int M, int relu, int out_bf16) {
    __shared__ unsigned As[128 * AS_STR];
    __shared__ unsigned Bst[128 * BT_STR];
    int m0 = bid * 128;
    int tid = threadIdx.x;
    int lane = tid & 31, wid = tid >> 5;
    int wm = wid & 3, wn = wid >> 2;
    int gid = lane >> 2, tig = lane & 3;

    float c[2][8][4];
#pragma unroll
    for (int mt = 0; mt < 2; mt++)
#pragma unroll
        for (int nt = 0; nt < 8; nt++)
#pragma unroll
            for (int q = 0; q < 4; q++) c[mt][nt][q] = 0.f;

    int ar = tid >> 1, acb = (tid & 1) * 16;
    int bn = tid & 127, bkh = (tid >> 7) * 16;

    const unsigned* pa0 = &As[(wm * 32 + (lane & 15)) * AS_STR + ((lane >> 4) << 2)];
    const unsigned* pa1 = pa0 + 16 * AS_STR;
    const unsigned* pb  = &Bst[(wn * 64 + ((lane >> 4) << 3) + (lane & 7)) * BT_STR +
                               (((lane >> 3) & 1) << 2)];

    for (int kc = 0; kc < 128; kc += 32) {
        {
            int grow = m0 + ar;
#pragma unroll
            for (int q = 0; q < 2; q++) {
                float4 v0 = (grow < M)
                    ? *(const float4*)&A[(size_t)grow * 128 + kc + acb + q * 8]
                    : make_float4(0.f, 0.f, 0.f, 0.f);
                float4 v1 = (grow < M)
                    ? *(const float4*)&A[(size_t)grow * 128 + kc + acb + q * 8 + 4]
                    : make_float4(0.f, 0.f, 0.f, 0.f);
                *(uint4*)&As[ar * AS_STR + acb + q * 8] =
                    make_uint4(f2tf(v0.x), f2tf(v0.y), f2tf(v0.z), f2tf(v0.w));
                *(uint4*)&As[ar * AS_STR + acb + q * 8 + 4] =
                    make_uint4(f2tf(v1.x), f2tf(v1.y), f2tf(v1.z), f2tf(v1.w));
            }
#pragma unroll
            for (int q = 0; q < 4; q++) {
                int kk = bkh + q * 4;
                uint4 u;
                u.x = f2tf(B[(size_t)(kc + kk + 0) * 128 + bn]);
                u.y = f2tf(B[(size_t)(kc + kk + 1) * 128 + bn]);
                u.z = f2tf(B[(size_t)(kc + kk + 2) * 128 + bn]);
                u.w = f2tf(B[(size_t)(kc + kk + 3) * 128 + bn]);
                *(uint4*)&Bst[bn * BT_STR + kk] = u;
            }
        }
        __syncthreads();
#pragma unroll
        for (int ks = 0; ks < 4; ks++) {
            int kb = ks * 8;
            unsigned a[2][4], b[8][2];
            ldsm4(a[0], pa0 + kb);
            ldsm4(a[1], pa1 + kb);
#pragma unroll
            for (int p = 0; p < 4; p++) {
                unsigned t4[4];
                ldsm4(t4, pb + p * 16 * BT_STR + kb);
                b[2 * p][0] = t4[0]; b[2 * p][1] = t4[1];
                b[2 * p + 1][0] = t4[2]; b[2 * p + 1][1] = t4[3];
            }
#pragma unroll
            for (int mt = 0; mt < 2; mt++)
#pragma unroll
                for (int nt = 0; nt < 8; nt++) mma8(c[mt][nt], a[mt], b[nt]);
        }
        __syncthreads();
    }

    __nv_bfloat16* Cb = (__nv_bfloat16*)C;
#pragma unroll
    for (int mt = 0; mt < 2; mt++) {
        int r = m0 + wm * 32 + mt * 16 + gid;
#pragma unroll
        for (int nt = 0; nt < 8; nt++) {
            int col = wn * 64 + nt * 8 + 2 * tig;
            float2 v0 = make_float2(c[mt][nt][0], c[mt][nt][1]);
            float2 v1 = make_float2(c[mt][nt][2], c[mt][nt][3]);
            if (relu) {
                v0.x = fmaxf(v0.x, 0.f); v0.y = fmaxf(v0.y, 0.f);
                v1.x = fmaxf(v1.x, 0.f); v1.y = fmaxf(v1.y, 0.f);
            }
            if (out_bf16) {
                __nv_bfloat162 b0 = __float22bfloat162_rn(v0);
                __nv_bfloat162 b1 = __float22bfloat162_rn(v1);
                if (r < M)     *(__nv_bfloat162*)&Cb[(size_t)r * 128 + col] = b0;
                if (r + 8 < M) *(__nv_bfloat162*)&Cb[(size_t)(r + 8) * 128 + col] = b1;
            } else {
                if (r < M)     *(float2*)&C[(size_t)r * 128 + col] = v0;
                if (r + 8 < M) *(float2*)&C[(size_t)(r + 8) * 128 + col] = v1;
            }
        }
    }
}

__global__ void __launch_bounds__(256)
k_gemm_tf32(const float* __restrict__ A, const float* __restrict__ B,
            float* __restrict__ C, int M, int relu, int out_bf16) {
    gemm_body(blockIdx.x, A, B, C, M, relu, out_bf16);
}

// ---------------- fused F1: gemm_t (x@W1t -> buf1 bf16) || zero arrays -------------
#define F1_CSR 256
__global__ void __launch_bounds__(256)
k_f1(const float* __restrict__ x, const float* __restrict__ W1t) {
    if (blockIdx.x < GM) {
        gemm_body(blockIdx.x, x, W1t, g_buf1, N_NODES, 0, 1);
        return;
    }
    int stride = F1_CSR * 256;
    for (int i = (blockIdx.x - GM) * 256 + threadIdx.x; i < N_NODES; i += stride) {
        g_cnt[i] = 0;
        g_flag[i] = 0;
        g_tflag[i] = 0;
    }
}

// ---------------- fused F2: gemm_c (mx@W1c -> buf2 bf16) || count ------------------
#define F2_CSR 512
__global__ void __launch_bounds__(256)
k_f2(const float* __restrict__ mx, const float* __restrict__ W1c,
     const int* __restrict__ dst) {
    if (blockIdx.x < GM) {
        gemm_body(blockIdx.x, mx, W1c, g_buf2, N_NODES, 0, 1);
        return;
    }
    int stride = F2_CSR * 256;
    for (int e = (blockIdx.x - GM) * 256 + threadIdx.x; e < N_EDGES; e += stride)
        atomicAdd(&g_cnt[dst[e]], 1);
}

// ---------------- scan (+ fused prep) ----------------
__global__ void k_scan() {
    __shared__ int sums[1024];
    const int CH = (N_NODES + 1024) / 1024;
    int t = threadIdx.x;
    int base = t * CH;
    int s = 0;
    for (int i = 0; i < CH; i++) {
        int idx = base + i;
        if (idx < N_NODES) s += g_cnt[idx];
    }
    sums[t] = s;
    __syncthreads();
    for (int off = 1; off < 1024; off <<= 1) {
        int v = (t >= off) ? sums[t - off] : 0;
        __syncthreads();
        sums[t] += v;
        __syncthreads();
    }
    int run = sums[t] - s;
    for (int i = 0; i < CH; i++) {
        int idx = base + i;
        if (idx <= N_NODES) g_rowptr[idx] = run;
        if (idx < N_NODES) {
            g_cursor[idx] = run;
            int c = g_cnt[idx];
            g_invdeg[idx] = 1.0f / (float)(c > 0 ? c : 1);
            run += c;
        }
    }
}

// ---------------- fused F3: fill || pe || wf->wt1 || zb || flag || wt2 || wt1ch4 ---
#define F3_FILL 1024
#define F3_PE   391
#define F3_WF   128
#define F3_WT2  128
// layout: fill | pe | wf | zb | flag(512) | wt2 | wt1-chunk4(1)
#define F3_GRID (F3_FILL + F3_PE + F3_WF + 1 + 512 + F3_WT2 + 1)
__global__ void __launch_bounds__(256)
k_f3(const int* __restrict__ src, const int* __restrict__ dst,
     const float* __restrict__ pos_enc, const float* __restrict__ Wpe,
     const float* __restrict__ W2c, const float* __restrict__ Wp1,
     const float* __restrict__ z, const float* __restrict__ bp1,
     const int* __restrict__ pair_s, const float* __restrict__ mask,
     const float* __restrict__ Wp2) {
    int b = blockIdx.x, tid = threadIdx.x;
    if (b < F3_FILL) {
        int stride = F3_FILL * 256;
        for (int e = b * 256 + tid; e < N_EDGES; e += stride) {
            int pos = atomicAdd(&g_cursor[dst[e]], 1);
            g_col[pos] = src[e];
        }
    } else if (b < F3_FILL + F3_PE) {
        int n = (b - F3_FILL) * 256 + tid;
        if (n < N_NODES) {
            float4 p = *(const float4*)&pos_enc[n * 4];
#pragma unroll
            for (int i = 0; i < 4; i++) {
                g_pe[n * 4 + i] = p.x * Wpe[i * 4 + 0] + p.y * Wpe[i * 4 + 1] +
                                  p.z * Wpe[i * 4 + 2] + p.w * Wpe[i * 4 + 3];
            }
        }
    } else if (b < F3_FILL + F3_PE + F3_WF) {
        // wf[k][n] = (W2c @ Wp1)[k][n], written chunk-major tf32 into g_wt1
        int k = b - F3_FILL - F3_PE;   // 0..127
        int j = tid;                    // 0..255
        float acc = 0.f;
        for (int d = 0; d < DIM; d++)
            acc = fmaf(W2c[k * DIM + d], Wp1[d * HP + j], acc);
        g_wt1[(k >> 5) * 8192 + j * 32 + (k & 31)] = f2tf(acc);
    } else if (b < F3_FILL + F3_PE + F3_WF + 1) {
        int j = tid;
        float acc = bp1[j];
        for (int i = 0; i < ZDIM; i++)
            acc = fmaf(z[i], Wp1[(128 + i) * HP + j], acc);
        g_zb[j] = acc;
    } else if (b < F3_FILL + F3_PE + F3_WF + 1 + 512) {
        int i = (b - F3_FILL - F3_PE - F3_WF - 1) * 256 + tid;
        if (i < P_PAIRS && mask[i] != 0.f) g_flag[pair_s[i]] = 1;
    } else if (b < F3_FILL + F3_PE + F3_WF + 1 + 512 + F3_WT2) {
        // Wp2 -> chunk-major tf32: g_wt2[(k>>5)*4096 + j*32 + (k&31)]
        int flat = (b - F3_FILL - F3_PE - F3_WF - 1 - 512) * 256 + tid;  // < 32768
        int k = flat >> 7, j = flat & 127;
        g_wt2[(k >> 5) * 4096 + j * 32 + (k & 31)] = f2tf(Wp2[(size_t)k * 128 + j]);
    } else {
        // Wp1 rows 192..199 -> g_wt1 chunk 4: [n(256)][kk(8)]
        int j = tid;
#pragma unroll
        for (int kk = 0; kk < 8; kk++)
            g_wt1[4 * 8192 + j * 8 + kk] = f2tf(Wp1[(size_t)(192 + kk) * 256 + j]);
    }
}

__global__ void k_tflag(const int* __restrict__ tgt) {
    int b = blockIdx.x * blockDim.x + threadIdx.x;
    if (b >= T_NODES) return;
    int n = tgt[b];
    int e = g_rowptr[n + 1];
    for (int i = g_rowptr[n]; i < e; i++) g_tflag[g_col[i]] = 1;
}

// ---------------- agg bodies ----------------
__device__ __forceinline__ void agg_node(const float* __restrict__ in, int n, int lane,
                                         float4& r) {
    int s = g_rowptr[n], e = g_rowptr[n + 1];
    float4 a0 = make_float4(0.f, 0.f, 0.f, 0.f), a1 = a0, a2 = a0, a3 = a0;
    int i = s;
    for (; i + 4 <= e; i += 4) {
        int c0 = g_col[i], c1 = g_col[i + 1], c2 = g_col[i + 2], c3 = g_col[i + 3];
        float4 v0 = *(const float4*)&in[(size_t)c0 * 128 + lane * 4];
        float4 v1 = *(const float4*)&in[(size_t)c1 * 128 + lane * 4];
        float4 v2 = *(const float4*)&in[(size_t)c2 * 128 + lane * 4];
        float4 v3 = *(const float4*)&in[(size_t)c3 * 128 + lane * 4];
        a0.x += v0.x; a0.y += v0.y; a0.z += v0.z; a0.w += v0.w;
        a1.x += v1.x; a1.y += v1.y; a1.z += v1.z; a1.w += v1.w;
        a2.x += v2.x; a2.y += v2.y; a2.z += v2.z; a2.w += v2.w;
        a3.x += v3.x; a3.y += v3.y; a3.z += v3.z; a3.w += v3.w;
    }
    for (; i < e; i++) {
        int c = g_col[i];
        float4 v = *(const float4*)&in[(size_t)c * 128 + lane * 4];
        a0.x += v.x; a0.y += v.y; a0.z += v.z; a0.w += v.w;
    }
    float inv = g_invdeg[n];
    r.x = (a0.x + a1.x + a2.x + a3.x) * inv;
    r.y = (a0.y + a1.y + a2.y + a3.y) * inv;
    r.z = (a0.z + a1.z + a2.z + a3.z) * inv;
    r.w = (a0.w + a1.w + a2.w + a3.w) * inv;
}

__device__ __forceinline__ void agg_node_bf16(const __nv_bfloat16* __restrict__ in,
                                              int n, int lane, float4& r) {
    int s = g_rowptr[n], e = g_rowptr[n + 1];
    float4 a0 = make_float4(0.f, 0.f, 0.f, 0.f), a1 = a0, a2 = a0, a3 = a0;
    int i = s;
    for (; i + 4 <= e; i += 4) {
        int c0 = g_col[i], c1 = g_col[i + 1], c2 = g_col[i + 2], c3 = g_col[i + 3];
        float4 v0 = bf4_load(&in[(size_t)c0 * 128 + lane * 4]);
        float4 v1 = bf4_load(&in[(size_t)c1 * 128 + lane * 4]);
        float4 v2 = bf4_load(&in[(size_t)c2 * 128 + lane * 4]);
        float4 v3 = bf4_load(&in[(size_t)c3 * 128 + lane * 4]);
        a0.x += v0.x; a0.y += v0.y; a0.z += v0.z; a0.w += v0.w;
        a1.x += v1.x; a1.y += v1.y; a1.z += v1.z; a1.w += v1.w;
        a2.x += v2.x; a2.y += v2.y; a2.z += v2.z; a2.w += v2.w;
        a3.x += v3.x; a3.y += v3.y; a3.z += v3.z; a3.w += v3.w;
    }
    for (; i < e; i++) {
        int c = g_col[i];
        float4 v = bf4_load(&in[(size_t)c * 128 + lane * 4]);
        a0.x += v.x; a0.y += v.y; a0.z += v.z; a0.w += v.w;
    }
    float inv = g_invdeg[n];
    r.x = (a0.x + a1.x + a2.x + a3.x) * inv;
    r.y = (a0.y + a1.y + a2.y + a3.y) * inv;
    r.z = (a0.z + a1.z + a2.z + a3.z) * inv;
    r.w = (a0.w + a1.w + a2.w + a3.w) * inv;
}

// ---------------- fused F4: agg_b2b (h_c) || agg_tflagged (ht) ---------------------
#define AGG_GRID 12500
__global__ void __launch_bounds__(256)
k_f4() {
    int b = blockIdx.x;
    int lane = threadIdx.x & 31;
    if (b < AGG_GRID) {
        int n = b * 8 + (threadIdx.x >> 5);
        if (n >= N_NODES) return;
        float4 r;
        agg_node_bf16((const __nv_bfloat16*)g_buf2, n, lane, r);
        r.x = fmaxf(r.x, 0.f); r.y = fmaxf(r.y, 0.f);
        r.z = fmaxf(r.z, 0.f); r.w = fmaxf(r.w, 0.f);
        bf4_store(&((__nv_bfloat16*)g_buf4)[(size_t)n * 128 + lane * 4], r);
    } else {
        int n = (b - AGG_GRID) * 8 + (threadIdx.x >> 5);
        if (n >= N_NODES) return;
        if (!g_tflag[n]) return;
        float4 r;
        agg_node_bf16((const __nv_bfloat16*)g_buf1, n, lane, r);
        r.x = fmaxf(r.x, 0.f); r.y = fmaxf(r.y, 0.f);
        r.z = fmaxf(r.z, 0.f); r.w = fmaxf(r.w, 0.f);
        *(float4*)&g_buf3[(size_t)n * 128 + lane * 4] = r;
    }
}

// ---------------- fused F5: agg_flagged (m) || agg_target --------------------------
#define F5_TGT ((T_NODES + 7) / 8)
__global__ void __launch_bounds__(256)
k_f5(const int* __restrict__ tgt) {
    int b = blockIdx.x;
    int lane = threadIdx.x & 31;
    if (b < AGG_GRID) {
        int n = b * 8 + (threadIdx.x >> 5);
        if (n >= N_NODES) return;
        if (!g_flag[n]) return;
        float4 r;
        agg_node_bf16((const __nv_bfloat16*)g_buf4, n, lane, r);
        *(float4*)&g_buf1[(size_t)n * 128 + lane * 4] = r;
    } else {
        int t = (b - AGG_GRID) * 8 + (threadIdx.x >> 5);
        if (t >= T_NODES) return;
        int n = tgt[t];
        float4 r;
        agg_node(g_buf3, n, lane, r);
        *(float4*)&g_tbuf[(size_t)t * 128 + lane * 4] = r;
    }
}

// ---------------- fused predictor (tf32 MMA + ldmatrix; pre-converted weights) -----
#define FS_STR 140
#define WT_STR 36
#define HID_STR 260
#define PRED_SMEM_UINTS (64 * HID_STR + 128 * WT_STR)
#define PRED_SMEM (PRED_SMEM_UINTS * 4)

__global__ void __launch_bounds__(256)
k_pred(const float* __restrict__ m, const int* __restrict__ pair_s,
       const int* __restrict__ pair_t, const int* __restrict__ tgt,
       const float* __restrict__ mask, const float* __restrict__ Wp2_unused,
       const float* __restrict__ bp2, float* __restrict__ out) {
    extern __shared__ unsigned sm[];
    int r0 = blockIdx.x * 64;
    int tid = threadIdx.x;
    __shared__ float ms[64];
    if (tid < 64) ms[tid] = mask[r0 + tid];
    int any = __syncthreads_or(tid < 64 && mask[r0 + tid] != 0.f);
    if (!any) {
        float4 zero = make_float4(0.f, 0.f, 0.f, 0.f);
#pragma unroll
        for (int i = 0; i < 8; i++) {
            int idx = tid + i * 256;
            *(float4*)&out[(size_t)r0 * 128 + idx * 4] = zero;
        }
        return;
    }

    unsigned* feats = sm;
    unsigned* wst   = sm + 64 * FS_STR;
    unsigned* hid   = sm;
    unsigned* ws2t  = sm + 64 * HID_STR;

    int lane = tid & 31, wid = tid >> 5;
    int wm = wid & 1, wn = wid >> 1;
    int gid = lane >> 2, tig = lane & 3;

    const unsigned* pfa = &feats[(wm * 32 + (lane & 15)) * FS_STR + ((lane >> 4) << 2)];
    const unsigned* pwb = &wst[(wn * 64 + ((lane >> 4) << 3) + (lane & 7)) * WT_STR +
                               (((lane >> 3) & 1) << 2)];
    const unsigned* pha = &hid[(wm * 32 + (lane & 15)) * HID_STR + ((lane >> 4) << 2)];
    const unsigned* pw2b = &ws2t[(wn * 32 + ((lane >> 4) << 3) + (lane & 7)) * WT_STR +
                                 (((lane >> 3) & 1) << 2)];

#pragma unroll
    for (int i = 0; i < 8; i++) {
        int idx = tid + i * 256;
        int r = idx >> 5, q = (idx & 31) << 2;
        int sN = pair_s[r0 + r];
        float4 v = *(const float4*)&m[(size_t)sN * 128 + q];
        uint4 u = make_uint4(f2tf(v.x), f2tf(v.y), f2tf(v.z), f2tf(v.w));
        *(uint4*)&feats[r * FS_STR + q] = u;
    }
    if (tid < 64) {
        int sN = pair_s[r0 + tid];
        int tN = tgt[pair_t[r0 + tid]];
        float4 ps = *(const float4*)&g_pe[sN * 4];
        float4 pt = *(const float4*)&g_pe[tN * 4];
        *(uint4*)&feats[tid * FS_STR + 128] =
            make_uint4(f2tf(ps.x), f2tf(ps.y), f2tf(ps.z), f2tf(ps.w));
        *(uint4*)&feats[tid * FS_STR + 132] =
            make_uint4(f2tf(pt.x), f2tf(pt.y), f2tf(pt.z), f2tf(pt.w));
    }

    float c[2][8][4];
#pragma unroll
    for (int mt = 0; mt < 2; mt++)
#pragma unroll
        for (int nt = 0; nt < 8; nt++)
#pragma unroll
            for (int q = 0; q < 4; q++) c[mt][nt][q] = 0.f;

    for (int ch = 0; ch < 5; ch++) {
        // coalesced copy of pre-converted weights into [n][k_local] stride 36
        if (ch < 4) {
            const unsigned* src = &g_wt1[ch * 8192];
#pragma unroll
            for (int j = 0; j < 8; j++) {
                uint4 u = *(const uint4*)&src[(j * 256 + tid) * 4];
                int n = j * 32 + (tid >> 3), kk = (tid & 7) * 4;
                *(uint4*)&wst[n * WT_STR + kk] = u;
            }
        } else {
            const unsigned* src = &g_wt1[4 * 8192];
#pragma unroll
            for (int j = 0; j < 2; j++) {
                int idx = j * 256 + tid;
                uint4 u = *(const uint4*)&src[idx * 4];
                int n = idx >> 1, kk = (idx & 1) * 4;
                *(uint4*)&wst[n * WT_STR + kk] = u;
            }
        }
        __syncthreads();
        int nks = (ch < 4) ? 4 : 1;
        for (int ks = 0; ks < nks; ks++) {
            int kb = ch * 32 + ks * 8;
            int kl = ks * 8;
            unsigned a[2][4], b[8][2];
            ldsm4(a[0], pfa + kb);
            ldsm4(a[1], pfa + 16 * FS_STR + kb);
#pragma unroll
            for (int p = 0; p < 4; p++) {
                unsigned t4[4];
                ldsm4(t4, pwb + p * 16 * WT_STR + kl);
                b[2 * p][0] = t4[0]; b[2 * p][1] = t4[1];
                b[2 * p + 1][0] = t4[2]; b[2 * p + 1][1] = t4[3];
            }
#pragma unroll
            for (int mt = 0; mt < 2; mt++)
#pragma unroll
                for (int nt = 0; nt < 8; nt++) mma8(c[mt][nt], a[mt], b[nt]);
        }
        __syncthreads();
    }

#pragma unroll
    for (int mt = 0; mt < 2; mt++) {
        int r = wm * 32 + mt * 16 + gid;
#pragma unroll
        for (int nt = 0; nt < 8; nt++) {
            int col = wn * 64 + nt * 8 + 2 * tig;
            float2 zbv = *(const float2*)&g_zb[col];
            uint2 u0 = make_uint2(f2tf(fmaxf(c[mt][nt][0] + zbv.x, 0.f)),
                                  f2tf(fmaxf(c[mt][nt][1] + zbv.y, 0.f)));
            uint2 u1 = make_uint2(f2tf(fmaxf(c[mt][nt][2] + zbv.x, 0.f)),
                                  f2tf(fmaxf(c[mt][nt][3] + zbv.y, 0.f)));
            *(uint2*)&hid[r * HID_STR + col] = u0;
            *(uint2*)&hid[(r + 8) * HID_STR + col] = u1;
        }
    }
    __syncthreads();

    float c2[2][4][4];
#pragma unroll
    for (int mt = 0; mt < 2; mt++)
#pragma unroll
        for (int nt = 0; nt < 4; nt++)
#pragma unroll
            for (int q = 0; q < 4; q++) c2[mt][nt][q] = 0.f;

    for (int ch = 0; ch < 8; ch++) {
        {
            const unsigned* src = &g_wt2[ch * 4096];
#pragma unroll
            for (int j = 0; j < 4; j++) {
                uint4 u = *(const uint4*)&src[(j * 256 + tid) * 4];
                int n = j * 32 + (tid >> 3), kk = (tid & 7) * 4;
                *(uint4*)&ws2t[n * WT_STR + kk] = u;
            }
        }
        __syncthreads();
#pragma unroll
        for (int ks = 0; ks < 4; ks++) {
            int kb = ch * 32 + ks * 8;
            int kl = ks * 8;
            unsigned a[2][4], b[4][2];
            ldsm4(a[0], pha + kb);
            ldsm4(a[1], pha + 16 * HID_STR + kb);
#pragma unroll
            for (int p = 0; p < 2; p++) {
                unsigned t4[4];
                ldsm4(t4, pw2b + p * 16 * WT_STR + kl);
                b[2 * p][0] = t4[0]; b[2 * p][1] = t4[1];
                b[2 * p + 1][0] = t4[2]; b[2 * p + 1][1] = t4[3];
            }
#pragma unroll
            for (int mt = 0; mt < 2; mt++)
#pragma unroll
                for (int nt = 0; nt < 4; nt++) mma8(c2[mt][nt], a[mt], b[nt]);
        }
        __syncthreads();
    }

#pragma unroll
    for (int mt = 0; mt < 2; mt++) {
        int lr = wm * 32 + mt * 16 + gid;
        float m0v = ms[lr], m1v = ms[lr + 8];
#pragma unroll
        for (int nt = 0; nt < 4; nt++) {
            int col = wn * 32 + nt * 8 + 2 * tig;
            float2 bb = *(const float2*)&bp2[col];
            float2 v0 = make_float2((c2[mt][nt][0] + bb.x) * m0v,
                                    (c2[mt][nt][1] + bb.y) * m0v);
            float2 v1 = make_float2((c2[mt][nt][2] + bb.x) * m1v,
                                    (c2[mt][nt][3] + bb.y) * m1v);
            *(float2*)&out[(size_t)(r0 + lr) * 128 + col] = v0;
            *(float2*)&out[(size_t)(r0 + lr + 8) * 128 + col] = v1;
        }
    }
}

// ---------------- launch ----------------
extern "C" void kernel_launch(void* const* d_in, const int* in_sizes, int n_in,
                              void* d_out, int out_size) {
    const float* x            = (const float*)d_in[0];
    const float* masked_x     = (const float*)d_in[1];
    const float* pos_enc      = (const float*)d_in[2];
    const int*   edge_src     = (const int*)d_in[3];
    const int*   edge_dst     = (const int*)d_in[4];
    const int*   target_nodes = (const int*)d_in[5];
    const int*   pair_t       = (const int*)d_in[6];
    const int*   pair_s       = (const int*)d_in[7];
    const float* pair_mask    = (const float*)d_in[8];
    const float* W1t          = (const float*)d_in[9];
    const float* W2t          = (const float*)d_in[10];
    const float* W1c          = (const float*)d_in[11];
    const float* W2c          = (const float*)d_in[12];
    const float* Wpe          = (const float*)d_in[13];
    const float* z            = (const float*)d_in[14];
    const float* Wp1          = (const float*)d_in[15];
    const float* bp1          = (const float*)d_in[16];
    const float* Wp2          = (const float*)d_in[17];
    const float* bp2          = (const float*)d_in[18];
    float* out = (float*)d_out;

    float *buf1, *tbuf;
    cudaGetSymbolAddress((void**)&buf1, g_buf1);
    cudaGetSymbolAddress((void**)&tbuf, g_tbuf);

    cudaFuncSetAttribute(k_pred, cudaFuncAttributeMaxDynamicSharedMemorySize,
                         PRED_SMEM);

    const int TPB = 256;

    // F1: gemm_t || zero(cnt/flag/tflag)
    k_f1<<<GM + F1_CSR, TPB>>>(x, W1t);
    // F2: gemm_c || count
    k_f2<<<GM + F2_CSR, TPB>>>(masked_x, W1c, edge_dst);
    // scan (+ fused prep)
    k_scan<<<1, 1024>>>();
    // F3: fill || pe || wf->wt1 || zb || flag || wt2 || wt1-chunk4
    k_f3<<<F3_GRID, TPB>>>(edge_src, edge_dst, pos_enc, Wpe, W2c, Wp1, z, bp1,
                           pair_s, pair_mask, Wp2);
    // tflag (needs fill)
    k_tflag<<<(T_NODES + TPB - 1) / TPB, TPB>>>(target_nodes);
    // F4: h_c agg || ht agg
    k_f4<<<AGG_GRID * 2, TPB>>>();
    // F5: m agg || target agg
    k_f5<<<AGG_GRID + F5_TGT, TPB>>>(target_nodes);
    // target tail: tiny GEMM straight into output embeddings
    k_gemm_tf32<<<T_NODES / 128, TPB>>>(tbuf, W2t, out + (size_t)P_PAIRS * DOUT,
                                        T_NODES, 0, 0);
    // fused predictor MLP (pre-converted weights)
    k_pred<<<P_PAIRS / 64, TPB, PRED_SMEM>>>(buf1, pair_s, pair_t, target_nodes,
                                             pair_mask, Wp2, bp2, out);
}

// round 16
// speedup vs baseline: 1.2368x; 1.2368x over previous
#include <cuda_runtime.h>
#include <cuda_bf16.h>
#include <cstdint>

#define N_NODES 100000
#define N_EDGES 1600000
#define DIM     128
#define T_NODES 4096
#define P_PAIRS 131072
#define HP      256
#define DOUT    128
#define ZDIM    64

// ---------------- scratch (static device globals; no allocation) ----------------
__device__ int   g_cnt[N_NODES];
__device__ int   g_rowptr[N_NODES + 1];
__device__ int   g_cursor[N_NODES];
__device__ int   g_col[N_EDGES];
__device__ float g_invdeg[N_NODES];
__device__ unsigned char g_flag[N_NODES];
__device__ unsigned char g_tflag[N_NODES];
__device__ float g_pe[N_NODES * 4];
__device__ float g_zb[HP];
__device__ float g_wf[DIM * HP];                    // W2c @ Wp1[0:128]
__device__ float g_buf1[(size_t)N_NODES * DIM];    // gemm_t out (bf16) -> later m (fp32)
__device__ float g_buf2[(size_t)N_NODES * DIM];    // gemm_c out (bf16)
__device__ float g_buf3[(size_t)N_NODES * DIM];    // ht (fp32, tflag rows)
__device__ float g_buf4[(size_t)N_NODES * DIM];    // h_c (bf16)
__device__ float g_tbuf[(size_t)T_NODES * DIM];

// ---------------- tf32 / mma / bf16 helpers ----------------
__device__ __forceinline__ unsigned f2tf(float f) {
    unsigned u;
    asm("cvt.rna.tf32.f32 %0, %1;" : "=r"(u) : "f"(f));
    return u;
}
__device__ __forceinline__ void mma8(float* c, const unsigned* a, const unsigned* b) {
    asm volatile(
        "mma.sync.aligned.m16n8k8.row.col.f32.tf32.tf32.f32 "
        "{%0,%1,%2,%3},{%4,%5,%6,%7},{%8,%9},{%0,%1,%2,%3};"
        : "+f"(c[0]), "+f"(c[1]), "+f"(c[2]), "+f"(c[3])
        : "r"(a[0]), "r"(a[1]), "r"(a[2]), "r"(a[3]), "r"(b[0]), "r"(b[1]));
}
__device__ __forceinline__ void ldsm4(unsigned* r, const unsigned* p) {
    unsigned addr = (unsigned)__cvta_generic_to_shared(p);
    asm volatile("ldmatrix.sync.aligned.m8n8.x4.shared.b16 {%0,%1,%2,%3}, [%4];"
                 : "=r"(r[0]), "=r"(r[1]), "=r"(r[2]), "=r"(r[3]) : "r"(addr));
}
__device__ __forceinline__ float4 bf4_load(const __nv_bfloat16* p) {
    uint2 u = *(const uint2*)p;
    __nv_bfloat162 a = *reinterpret_cast<const __nv_bfloat162*>(&u.x);
    __nv_bfloat162 b = *reinterpret_cast<const __nv_bfloat162*>(&u.y);
    float2 fa = __bfloat1622float2(a), fb = __bfloat1622float2(b);
    return make_float4(fa.x, fa.y, fb.x, fb.y);
}
__device__ __forceinline__ void bf4_store(__nv_bfloat16* p, float4 v) {
    __nv_bfloat162 a = __float22bfloat162_rn(make_float2(v.x, v.y));
    __nv_bfloat162 b = __float22bfloat162_rn(make_float2(v.z, v.w));
    uint2 u;
    u.x = *reinterpret_cast<unsigned*>(&a);
    u.y = *reinterpret_cast<unsigned*>(&b);
    *(uint2*)p = u;
}

// ---------------- GEMM body (R10-proven, ldmatrix) ----------------
#define AS_STR 36
#define BT_STR 36
#define GM 782   // gemm grid for M = N_NODES

__device__ void gemm_body(int bid, const float* __restrict__ A,
                          const float* __restrict__ B, float* __restrict__ C,
                          int M, int relu, int out_bf16) {
    __shared__ unsigned As[128 * AS_STR];
    __shared__ unsigned Bst[128 * BT_STR];
    int m0 = bid * 128;
    int tid = threadIdx.x;
    int lane = tid & 31, wid = tid >> 5;
    int wm = wid & 3, wn = wid >> 2;
    int gid = lane >> 2, tig = lane & 3;

    float c[2][8][4];
#pragma unroll
    for (int mt = 0; mt < 2; mt++)
#pragma unroll
        for (int nt = 0; nt < 8; nt++)
#pragma unroll
            for (int q = 0; q < 4; q++) c[mt][nt][q] = 0.f;

    int ar = tid >> 1, acb = (tid & 1) * 16;
    int bn = tid & 127, bkh = (tid >> 7) * 16;

    const unsigned* pa0 = &As[(wm * 32 + (lane & 15)) * AS_STR + ((lane >> 4) << 2)];
    const unsigned* pa1 = pa0 + 16 * AS_STR;
    const unsigned* pb  = &Bst[(wn * 64 + ((lane >> 4) << 3) + (lane & 7)) * BT_STR +
                               (((lane >> 3) & 1) << 2)];

    for (int kc = 0; kc < 128; kc += 32) {
        {
            int grow = m0 + ar;
#pragma unroll
            for (int q = 0; q < 2; q++) {
                float4 v0 = (grow < M)
                    ? *(const float4*)&A[(size_t)grow * 128 + kc + acb + q * 8]
                    : make_float4(0.f, 0.f, 0.f, 0.f);
                float4 v1 = (grow < M)
                    ? *(const float4*)&A[(size_t)grow * 128 + kc + acb + q * 8 + 4]
                    : make_float4(0.f, 0.f, 0.f, 0.f);
                *(uint4*)&As[ar * AS_STR + acb + q * 8] =
                    make_uint4(f2tf(v0.x), f2tf(v0.y), f2tf(v0.z), f2tf(v0.w));
                *(uint4*)&As[ar * AS_STR + acb + q * 8 + 4] =
                    make_uint4(f2tf(v1.x), f2tf(v1.y), f2tf(v1.z), f2tf(v1.w));
            }
#pragma unroll
            for (int q = 0; q < 4; q++) {
                int kk = bkh + q * 4;
                uint4 u;
                u.x = f2tf(B[(size_t)(kc + kk + 0) * 128 + bn]);
                u.y = f2tf(B[(size_t)(kc + kk + 1) * 128 + bn]);
                u.z = f2tf(B[(size_t)(kc + kk + 2) * 128 + bn]);
                u.w = f2tf(B[(size_t)(kc + kk + 3) * 128 + bn]);
                *(uint4*)&Bst[bn * BT_STR + kk] = u;
            }
        }
        __syncthreads();
#pragma unroll
        for (int ks = 0; ks < 4; ks++) {
            int kb = ks * 8;
            unsigned a[2][4], b[8][2];
            ldsm4(a[0], pa0 + kb);
            ldsm4(a[1], pa1 + kb);
#pragma unroll
            for (int p = 0; p < 4; p++) {
                unsigned t4[4];
                ldsm4(t4, pb + p * 16 * BT_STR + kb);
                b[2 * p][0] = t4[0]; b[2 * p][1] = t4[1];
                b[2 * p + 1][0] = t4[2]; b[2 * p + 1][1] = t4[3];
            }
#pragma unroll
            for (int mt = 0; mt < 2; mt++)
#pragma unroll
                for (int nt = 0; nt < 8; nt++) mma8(c[mt][nt], a[mt], b[nt]);
        }
        __syncthreads();
    }

    __nv_bfloat16* Cb = (__nv_bfloat16*)C;
#pragma unroll
    for (int mt = 0; mt < 2; mt++) {
        int r = m0 + wm * 32 + mt * 16 + gid;
#pragma unroll
        for (int nt = 0; nt < 8; nt++) {
            int col = wn * 64 + nt * 8 + 2 * tig;
            float2 v0 = make_float2(c[mt][nt][0], c[mt][nt][1]);
            float2 v1 = make_float2(c[mt][nt][2], c[mt][nt][3]);
            if (relu) {
                v0.x = fmaxf(v0.x, 0.f); v0.y = fmaxf(v0.y, 0.f);
                v1.x = fmaxf(v1.x, 0.f); v1.y = fmaxf(v1.y, 0.f);
            }
            if (out_bf16) {
                __nv_bfloat162 b0 = __float22bfloat162_rn(v0);
                __nv_bfloat162 b1 = __float22bfloat162_rn(v1);
                if (r < M)     *(__nv_bfloat162*)&Cb[(size_t)r * 128 + col] = b0;
                if (r + 8 < M) *(__nv_bfloat162*)&Cb[(size_t)(r + 8) * 128 + col] = b1;
            } else {
                if (r < M)     *(float2*)&C[(size_t)r * 128 + col] = v0;
                if (r + 8 < M) *(float2*)&C[(size_t)(r + 8) * 128 + col] = v1;
            }
        }
    }
}

__global__ void __launch_bounds__(256)
k_gemm_tf32(const float* __restrict__ A, const float* __restrict__ B,
            float* __restrict__ C, int M, int relu, int out_bf16) {
    gemm_body(blockIdx.x, A, B, C, M, relu, out_bf16);
}

// ---------------- fused F1: zero arrays (first) || gemm_t (x@W1t -> buf1 bf16) -----
// CSR blocks placed FIRST so they dispatch inside the GEMM's first wave.
#define F1_CSR 256
__global__ void __launch_bounds__(256)
k_f1(const float* __restrict__ x, const float* __restrict__ W1t) {
    if (blockIdx.x >= F1_CSR) {
        gemm_body(blockIdx.x - F1_CSR, x, W1t, g_buf1, N_NODES, 0, 1);
        return;
    }
    int stride = F1_CSR * 256;
    for (int i = blockIdx.x * 256 + threadIdx.x; i < N_NODES; i += stride) {
        g_cnt[i] = 0;
        g_flag[i] = 0;
        g_tflag[i] = 0;
    }
}

// ---------------- fused F2: count (first) || gemm_c (mx@W1c -> buf2 bf16) ----------
#define F2_CSR 512
__global__ void __launch_bounds__(256)
k_f2(const float* __restrict__ mx, const float* __restrict__ W1c,
     const int* __restrict__ dst) {
    if (blockIdx.x >= F2_CSR) {
        gemm_body(blockIdx.x - F2_CSR, mx, W1c, g_buf2, N_NODES, 0, 1);
        return;
    }
    int stride = F2_CSR * 256;
    for (int e = blockIdx.x * 256 + threadIdx.x; e < N_EDGES; e += stride)
        atomicAdd(&g_cnt[dst[e]], 1);
}

// ---------------- scan / prep (standalone) ----------------
__global__ void k_scan() {
    __shared__ int sums[1024];
    const int CH = (N_NODES + 1024) / 1024;
    int t = threadIdx.x;
    int base = t * CH;
    int s = 0;
    for (int i = 0; i < CH; i++) {
        int idx = base + i;
        if (idx < N_NODES) s += g_cnt[idx];
    }
    sums[t] = s;
    __syncthreads();
    for (int off = 1; off < 1024; off <<= 1) {
        int v = (t >= off) ? sums[t - off] : 0;
        __syncthreads();
        sums[t] += v;
        __syncthreads();
    }
    int run = sums[t] - s;
    for (int i = 0; i < CH; i++) {
        int idx = base + i;
        if (idx <= N_NODES) g_rowptr[idx] = run;
        if (idx < N_NODES) run += g_cnt[idx];
    }
}

__global__ void k_prep() {
    int i = blockIdx.x * blockDim.x + threadIdx.x;
    if (i < N_NODES) {
        g_cursor[i] = g_rowptr[i];
        int c = g_cnt[i];
        g_invdeg[i] = 1.0f / (float)(c > 0 ? c : 1);
    }
}

// ---------------- fused F3: fill || pe || wf || zb || flag -------------------------
#define F3_FILL 1024
#define F3_PE   391
#define F3_WF   128
#define F3_GRID (F3_FILL + F3_PE + F3_WF + 1 + 512)
__global__ void __launch_bounds__(256)
k_f3(const int* __restrict__ src, const int* __restrict__ dst,
     const float* __restrict__ pos_enc, const float* __restrict__ Wpe,
     const float* __restrict__ W2c, const float* __restrict__ Wp1,
     const float* __restrict__ z, const float* __restrict__ bp1,
     const int* __restrict__ pair_s, const float* __restrict__ mask) {
    int b = blockIdx.x, tid = threadIdx.x;
    if (b < F3_FILL) {
        int stride = F3_FILL * 256;
        for (int e = b * 256 + tid; e < N_EDGES; e += stride) {
            int pos = atomicAdd(&g_cursor[dst[e]], 1);
            g_col[pos] = src[e];
        }
    } else if (b < F3_FILL + F3_PE) {
        int n = (b - F3_FILL) * 256 + tid;
        if (n < N_NODES) {
            float4 p = *(const float4*)&pos_enc[n * 4];
#pragma unroll
            for (int i = 0; i < 4; i++) {
                g_pe[n * 4 + i] = p.x * Wpe[i * 4 + 0] + p.y * Wpe[i * 4 + 1] +
                                  p.z * Wpe[i * 4 + 2] + p.w * Wpe[i * 4 + 3];
            }
        }
    } else if (b < F3_FILL + F3_PE + F3_WF) {
        int i = b - F3_FILL - F3_PE;
        int j = tid;
        float acc = 0.f;
        for (int d = 0; d < DIM; d++)
            acc = fmaf(W2c[i * DIM + d], Wp1[d * HP + j], acc);
        g_wf[i * HP + j] = acc;
    } else if (b < F3_FILL + F3_PE + F3_WF + 1) {
        int j = tid;
        float acc = bp1[j];
        for (int i = 0; i < ZDIM; i++)
            acc = fmaf(z[i], Wp1[(128 + i) * HP + j], acc);
        g_zb[j] = acc;
    } else {
        int i = (b - F3_FILL - F3_PE - F3_WF - 1) * 256 + tid;
        if (i < P_PAIRS && mask[i] != 0.f) g_flag[pair_s[i]] = 1;
    }
}

__global__ void k_tflag(const int* __restrict__ tgt) {
    int b = blockIdx.x * blockDim.x + threadIdx.x;
    if (b >= T_NODES) return;
    int n = tgt[b];
    int e = g_rowptr[n + 1];
    for (int i = g_rowptr[n]; i < e; i++) g_tflag[g_col[i]] = 1;
}

// ---------------- agg bodies ----------------
__device__ __forceinline__ void agg_node(const float* __restrict__ in, int n, int lane,
                                         float4& r) {
    int s = g_rowptr[n], e = g_rowptr[n + 1];
    float4 a0 = make_float4(0.f, 0.f, 0.f, 0.f), a1 = a0, a2 = a0, a3 = a0;
    int i = s;
    for (; i + 4 <= e; i += 4) {
        int c0 = g_col[i], c1 = g_col[i + 1], c2 = g_col[i + 2], c3 = g_col[i + 3];
        float4 v0 = *(const float4*)&in[(size_t)c0 * 128 + lane * 4];
        float4 v1 = *(const float4*)&in[(size_t)c1 * 128 + lane * 4];
        float4 v2 = *(const float4*)&in[(size_t)c2 * 128 + lane * 4];
        float4 v3 = *(const float4*)&in[(size_t)c3 * 128 + lane * 4];
        a0.x += v0.x; a0.y += v0.y; a0.z += v0.z; a0.w += v0.w;
        a1.x += v1.x; a1.y += v1.y; a1.z += v1.z; a1.w += v1.w;
        a2.x += v2.x; a2.y += v2.y; a2.z += v2.z; a2.w += v2.w;
        a3.x += v3.x; a3.y += v3.y; a3.z += v3.z; a3.w += v3.w;
    }
    for (; i < e; i++) {
        int c = g_col[i];
        float4 v = *(const float4*)&in[(size_t)c * 128 + lane * 4];
        a0.x += v.x; a0.y += v.y; a0.z += v.z; a0.w += v.w;
    }
    float inv = g_invdeg[n];
    r.x = (a0.x + a1.x + a2.x + a3.x) * inv;
    r.y = (a0.y + a1.y + a2.y + a3.y) * inv;
    r.z = (a0.z + a1.z + a2.z + a3.z) * inv;
    r.w = (a0.w + a1.w + a2.w + a3.w) * inv;
}

__device__ __forceinline__ void agg_node_bf16(const __nv_bfloat16* __restrict__ in,
                                              int n, int lane, float4& r) {
    int s = g_rowptr[n], e = g_rowptr[n + 1];
    float4 a0 = make_float4(0.f, 0.f, 0.f, 0.f), a1 = a0, a2 = a0, a3 = a0;
    int i = s;
    for (; i + 4 <= e; i += 4) {
        int c0 = g_col[i], c1 = g_col[i + 1], c2 = g_col[i + 2], c3 = g_col[i + 3];
        float4 v0 = bf4_load(&in[(size_t)c0 * 128 + lane * 4]);
        float4 v1 = bf4_load(&in[(size_t)c1 * 128 + lane * 4]);
        float4 v2 = bf4_load(&in[(size_t)c2 * 128 + lane * 4]);
        float4 v3 = bf4_load(&in[(size_t)c3 * 128 + lane * 4]);
        a0.x += v0.x; a0.y += v0.y; a0.z += v0.z; a0.w += v0.w;
        a1.x += v1.x; a1.y += v1.y; a1.z += v1.z; a1.w += v1.w;
        a2.x += v2.x; a2.y += v2.y; a2.z += v2.z; a2.w += v2.w;
        a3.x += v3.x; a3.y += v3.y; a3.z += v3.z; a3.w += v3.w;
    }
    for (; i < e; i++) {
        int c = g_col[i];
        float4 v = bf4_load(&in[(size_t)c * 128 + lane * 4]);
        a0.x += v.x; a0.y += v.y; a0.z += v.z; a0.w += v.w;
    }
    float inv = g_invdeg[n];
    r.x = (a0.x + a1.x + a2.x + a3.x) * inv;
    r.y = (a0.y + a1.y + a2.y + a3.y) * inv;
    r.z = (a0.z + a1.z + a2.z + a3.z) * inv;
    r.w = (a0.w + a1.w + a2.w + a3.w) * inv;
}

// ---------------- fused F4: agg_b2b (h_c) || agg_tflagged (ht) ---------------------
#define AGG_GRID 12500
__global__ void __launch_bounds__(256)
k_f4() {
    int b = blockIdx.x;
    int lane = threadIdx.x & 31;
    if (b < AGG_GRID) {
        int n = b * 8 + (threadIdx.x >> 5);
        if (n >= N_NODES) return;
        float4 r;
        agg_node_bf16((const __nv_bfloat16*)g_buf2, n, lane, r);
        r.x = fmaxf(r.x, 0.f); r.y = fmaxf(r.y, 0.f);
        r.z = fmaxf(r.z, 0.f); r.w = fmaxf(r.w, 0.f);
        bf4_store(&((__nv_bfloat16*)g_buf4)[(size_t)n * 128 + lane * 4], r);
    } else {
        int n = (b - AGG_GRID) * 8 + (threadIdx.x >> 5);
        if (n >= N_NODES) return;
        if (!g_tflag[n]) return;
        float4 r;
        agg_node_bf16((const __nv_bfloat16*)g_buf1, n, lane, r);
        r.x = fmaxf(r.x, 0.f); r.y = fmaxf(r.y, 0.f);
        r.z = fmaxf(r.z, 0.f); r.w = fmaxf(r.w, 0.f);
        *(float4*)&g_buf3[(size_t)n * 128 + lane * 4] = r;
    }
}

// ---------------- fused F5: agg_flagged (m) || agg_target --------------------------
#define F5_TGT ((T_NODES + 7) / 8)
__global__ void __launch_bounds__(256)
k_f5(const int* __restrict__ tgt) {
    int b = blockIdx.x;
    int lane = threadIdx.x & 31;
    if (b < AGG_GRID) {
        int n = b * 8 + (threadIdx.x >> 5);
        if (n >= N_NODES) return;
        if (!g_flag[n]) return;
        float4 r;
        agg_node_bf16((const __nv_bfloat16*)g_buf4, n, lane, r);
        *(float4*)&g_buf1[(size_t)n * 128 + lane * 4] = r;
    } else {
        int t = (b - AGG_GRID) * 8 + (threadIdx.x >> 5);
        if (t >= T_NODES) return;
        int n = tgt[t];
        float4 r;
        agg_node(g_buf3, n, lane, r);
        *(float4*)&g_tbuf[(size_t)t * 128 + lane * 4] = r;
    }
}

// ---------------- fused predictor (tf32 MMA + ldmatrix, both layers) ---------------
#define FS_STR 140
#define WT_STR 36
#define HID_STR 260
#define PRED_SMEM_UINTS (64 * HID_STR + 128 * WT_STR)
#define PRED_SMEM (PRED_SMEM_UINTS * 4)

__global__ void __launch_bounds__(256)
k_pred(const float* __restrict__ m, const int* __restrict__ pair_s,
       const int* __restrict__ pair_t, const int* __restrict__ tgt,
       const float* __restrict__ mask, const float* __restrict__ Wp1,
       const float* __restrict__ Wp2, const float* __restrict__ bp2,
       float* __restrict__ out) {
    extern __shared__ unsigned sm[];
    int r0 = blockIdx.x * 64;
    int tid = threadIdx.x;
    __shared__ float ms[64];
    if (tid < 64) ms[tid] = mask[r0 + tid];
    int any = __syncthreads_or(tid < 64 && mask[r0 + tid] != 0.f);
    if (!any) {
        float4 zero = make_float4(0.f, 0.f, 0.f, 0.f);
#pragma unroll
        for (int i = 0; i < 8; i++) {
            int idx = tid + i * 256;
            *(float4*)&out[(size_t)r0 * 128 + idx * 4] = zero;
        }
        return;
    }

    unsigned* feats = sm;
    unsigned* wst   = sm + 64 * FS_STR;
    unsigned* hid   = sm;
    unsigned* ws2t  = sm + 64 * HID_STR;

    int lane = tid & 31, wid = tid >> 5;
    int wm = wid & 1, wn = wid >> 1;
    int gid = lane >> 2, tig = lane & 3;

    const unsigned* pfa = &feats[(wm * 32 + (lane & 15)) * FS_STR + ((lane >> 4) << 2)];
    const unsigned* pwb = &wst[(wn * 64 + ((lane >> 4) << 3) + (lane & 7)) * WT_STR +
                               (((lane >> 3) & 1) << 2)];
    const unsigned* pha = &hid[(wm * 32 + (lane & 15)) * HID_STR + ((lane >> 4) << 2)];
    const unsigned* pw2b = &ws2t[(wn * 32 + ((lane >> 4) << 3) + (lane & 7)) * WT_STR +
                                 (((lane >> 3) & 1) << 2)];

#pragma unroll
    for (int i = 0; i < 8; i++) {
        int idx = tid + i * 256;
        int r = idx >> 5, q = (idx & 31) << 2;
        int sN = pair_s[r0 + r];
        float4 v = *(const float4*)&m[(size_t)sN * 128 + q];
        uint4 u = make_uint4(f2tf(v.x), f2tf(v.y), f2tf(v.z), f2tf(v.w));
        *(uint4*)&feats[r * FS_STR + q] = u;
    }
    if (tid < 64) {
        int sN = pair_s[r0 + tid];
        int tN = tgt[pair_t[r0 + tid]];
        float4 ps = *(const float4*)&g_pe[sN * 4];
        float4 pt = *(const float4*)&g_pe[tN * 4];
        *(uint4*)&feats[tid * FS_STR + 128] =
            make_uint4(f2tf(ps.x), f2tf(ps.y), f2tf(ps.z), f2tf(ps.w));
        *(uint4*)&feats[tid * FS_STR + 132] =
            make_uint4(f2tf(pt.x), f2tf(pt.y), f2tf(pt.z), f2tf(pt.w));
    }

    float c[2][8][4];
#pragma unroll
    for (int mt = 0; mt < 2; mt++)
#pragma unroll
        for (int nt = 0; nt < 8; nt++)
#pragma unroll
            for (int q = 0; q < 4; q++) c[mt][nt][q] = 0.f;

    for (int ch = 0; ch < 5; ch++) {
        int nrows = (ch < 4) ? 32 : 8;
        {
            int n = tid;
            int nq = nrows >> 2;
#pragma unroll
            for (int q = 0; q < 8; q++) {
                if (q >= nq) break;
                int kk = q * 4;
                uint4 u;
                if (ch < 4) {
                    const float* base = &g_wf[(size_t)(ch * 32 + kk) * 256 + n];
                    u.x = f2tf(base[0]);
                    u.y = f2tf(base[256]);
                    u.z = f2tf(base[512]);
                    u.w = f2tf(base[768]);
                } else {
                    const float* base = &Wp1[(size_t)(192 + kk) * 256 + n];
                    u.x = f2tf(base[0]);
                    u.y = f2tf(base[256]);
                    u.z = f2tf(base[512]);
                    u.w = f2tf(base[768]);
                }
                *(uint4*)&wst[n * WT_STR + kk] = u;
            }
        }
        __syncthreads();
        int nks = nrows >> 3;
        for (int ks = 0; ks < nks; ks++) {
            int kb = ch * 32 + ks * 8;
            int kl = ks * 8;
            unsigned a[2][4], b[8][2];
            ldsm4(a[0], pfa + kb);
            ldsm4(a[1], pfa + 16 * FS_STR + kb);
#pragma unroll
            for (int p = 0; p < 4; p++) {
                unsigned t4[4];
                ldsm4(t4, pwb + p * 16 * WT_STR + kl);
                b[2 * p][0] = t4[0]; b[2 * p][1] = t4[1];
                b[2 * p + 1][0] = t4[2]; b[2 * p + 1][1] = t4[3];
            }
#pragma unroll
            for (int mt = 0; mt < 2; mt++)
#pragma unroll
                for (int nt = 0; nt < 8; nt++) mma8(c[mt][nt], a[mt], b[nt]);
        }
        __syncthreads();
    }

#pragma unroll
    for (int mt = 0; mt < 2; mt++) {
        int r = wm * 32 + mt * 16 + gid;
#pragma unroll
        for (int nt = 0; nt < 8; nt++) {
            int col = wn * 64 + nt * 8 + 2 * tig;
            float2 zbv = *(const float2*)&g_zb[col];
            uint2 u0 = make_uint2(f2tf(fmaxf(c[mt][nt][0] + zbv.x, 0.f)),
                                  f2tf(fmaxf(c[mt][nt][1] + zbv.y, 0.f)));
            uint2 u1 = make_uint2(f2tf(fmaxf(c[mt][nt][2] + zbv.x, 0.f)),
                                  f2tf(fmaxf(c[mt][nt][3] + zbv.y, 0.f)));
            *(uint2*)&hid[r * HID_STR + col] = u0;
            *(uint2*)&hid[(r + 8) * HID_STR + col] = u1;
        }
    }
    __syncthreads();

    float c2[2][4][4];
#pragma unroll
    for (int mt = 0; mt < 2; mt++)
#pragma unroll
        for (int nt = 0; nt < 4; nt++)
#pragma unroll
            for (int q = 0; q < 4; q++) c2[mt][nt][q] = 0.f;

    int w2n = tid & 127, w2kh = (tid >> 7) * 16;
    for (int ch = 0; ch < 8; ch++) {
        {
#pragma unroll
            for (int q = 0; q < 4; q++) {
                int kk = w2kh + q * 4;
                const float* base = &Wp2[(size_t)(ch * 32 + kk) * 128 + w2n];
                uint4 u;
                u.x = f2tf(base[0]);
                u.y = f2tf(base[128]);
                u.z = f2tf(base[256]);
                u.w = f2tf(base[384]);
                *(uint4*)&ws2t[w2n * WT_STR + kk] = u;
            }
        }
        __syncthreads();
#pragma unroll
        for (int ks = 0; ks < 4; ks++) {
            int kb = ch * 32 + ks * 8;
            int kl = ks * 8;
            unsigned a[2][4], b[4][2];
            ldsm4(a[0], pha + kb);
            ldsm4(a[1], pha + 16 * HID_STR + kb);
#pragma unroll
            for (int p = 0; p < 2; p++) {
                unsigned t4[4];
                ldsm4(t4, pw2b + p * 16 * WT_STR + kl);
                b[2 * p][0] = t4[0]; b[2 * p][1] = t4[1];
                b[2 * p + 1][0] = t4[2]; b[2 * p + 1][1] = t4[3];
            }
#pragma unroll
            for (int mt = 0; mt < 2; mt++)
#pragma unroll
                for (int nt = 0; nt < 4; nt++) mma8(c2[mt][nt], a[mt], b[nt]);
        }
        __syncthreads();
    }

#pragma unroll
    for (int mt = 0; mt < 2; mt++) {
        int lr = wm * 32 + mt * 16 + gid;
        float m0v = ms[lr], m1v = ms[lr + 8];
#pragma unroll
        for (int nt = 0; nt < 4; nt++) {
            int col = wn * 32 + nt * 8 + 2 * tig;
            float2 bb = *(const float2*)&bp2[col];
            float2 v0 = make_float2((c2[mt][nt][0] + bb.x) * m0v,
                                    (c2[mt][nt][1] + bb.y) * m0v);
            float2 v1 = make_float2((c2[mt][nt][2] + bb.x) * m1v,
                                    (c2[mt][nt][3] + bb.y) * m1v);
            *(float2*)&out[(size_t)(r0 + lr) * 128 + col] = v0;
            *(float2*)&out[(size_t)(r0 + lr + 8) * 128 + col] = v1;
        }
    }
}

// ---------------- launch ----------------
extern "C" void kernel_launch(void* const* d_in, const int* in_sizes, int n_in,
                              void* d_out, int out_size) {
    const float* x            = (const float*)d_in[0];
    const float* masked_x     = (const float*)d_in[1];
    const float* pos_enc      = (const float*)d_in[2];
    const int*   edge_src     = (const int*)d_in[3];
    const int*   edge_dst     = (const int*)d_in[4];
    const int*   target_nodes = (const int*)d_in[5];
    const int*   pair_t       = (const int*)d_in[6];
    const int*   pair_s       = (const int*)d_in[7];
    const float* pair_mask    = (const float*)d_in[8];
    const float* W1t          = (const float*)d_in[9];
    const float* W2t          = (const float*)d_in[10];
    const float* W1c          = (const float*)d_in[11];
    const float* W2c          = (const float*)d_in[12];
    const float* Wpe          = (const float*)d_in[13];
    const float* z            = (const float*)d_in[14];
    const float* Wp1          = (const float*)d_in[15];
    const float* bp1          = (const float*)d_in[16];
    const float* Wp2          = (const float*)d_in[17];
    const float* bp2          = (const float*)d_in[18];
    float* out = (float*)d_out;

    float *buf1, *tbuf;
    cudaGetSymbolAddress((void**)&buf1, g_buf1);
    cudaGetSymbolAddress((void**)&tbuf, g_tbuf);

    cudaFuncSetAttribute(k_pred, cudaFuncAttributeMaxDynamicSharedMemorySize,
                         PRED_SMEM);

    const int TPB = 256;

    // F1: zero(cnt/flag/tflag) first-wave || gemm_t
    k_f1<<<F1_CSR + GM, TPB>>>(x, W1t);
    // F2: count first-wave || gemm_c
    k_f2<<<F2_CSR + GM, TPB>>>(masked_x, W1c, edge_dst);
    // scan + prep
    k_scan<<<1, 1024>>>();
    k_prep<<<(N_NODES + TPB - 1) / TPB, TPB>>>();
    // F3: fill || pe || wf || zb || flag
    k_f3<<<F3_GRID, TPB>>>(edge_src, edge_dst, pos_enc, Wpe, W2c, Wp1, z, bp1,
                           pair_s, pair_mask);
    // tflag (needs fill)
    k_tflag<<<(T_NODES + TPB - 1) / TPB, TPB>>>(target_nodes);
    // F4: h_c agg || ht agg
    k_f4<<<AGG_GRID * 2, TPB>>>();
    // F5: m agg || target agg
    k_f5<<<AGG_GRID + F5_TGT, TPB>>>(target_nodes);
    // target tail: tiny GEMM straight into output embeddings
    k_gemm_tf32<<<T_NODES / 128, TPB>>>(tbuf, W2t, out + (size_t)P_PAIRS * DOUT,
                                        T_NODES, 0, 0);
    // fused predictor MLP
    k_pred<<<P_PAIRS / 64, TPB, PRED_SMEM>>>(buf1, pair_s, pair_t, target_nodes,
                                             pair_mask, Wp1, Wp2, bp2, out);
}

// round 17
// speedup vs baseline: 1.2767x; 1.0322x over previous
#include <cuda_runtime.h>
#include <cuda_bf16.h>
#include <cstdint>

#define N_NODES 100000
#define N_EDGES 1600000
#define DIM     128
#define T_NODES 4096
#define P_PAIRS 131072
#define HP      256
#define DOUT    128
#define ZDIM    64

// ---------------- scratch (static device globals; no allocation) ----------------
__device__ int   g_cnt[N_NODES];
__device__ int   g_rowptr[N_NODES + 1];
__device__ int   g_cursor[N_NODES];
__device__ int   g_col[N_EDGES];
__device__ float g_invdeg[N_NODES];
__device__ unsigned char g_flag[N_NODES];
__device__ unsigned char g_tflag[N_NODES];
__device__ unsigned char g_istgt[N_NODES];
__device__ float g_pe[N_NODES * 4];
__device__ float g_zb[HP];
__device__ float g_wf[DIM * HP];                    // W2c @ Wp1[0:128]
__device__ float g_buf1[(size_t)N_NODES * DIM];    // gemm_t out (bf16) -> later m (fp32)
__device__ float g_buf2[(size_t)N_NODES * DIM];    // gemm_c out (bf16)
__device__ float g_buf3[(size_t)N_NODES * DIM];    // ht (fp32, tflag rows)
__device__ float g_buf4[(size_t)N_NODES * DIM];    // h_c (bf16)
__device__ float g_tbuf[(size_t)T_NODES * DIM];

// ---------------- tf32 / mma / bf16 helpers ----------------
__device__ __forceinline__ unsigned f2tf(float f) {
    unsigned u;
    asm("cvt.rna.tf32.f32 %0, %1;" : "=r"(u) : "f"(f));
    return u;
}
__device__ __forceinline__ void mma8(float* c, const unsigned* a, const unsigned* b) {
    asm volatile(
        "mma.sync.aligned.m16n8k8.row.col.f32.tf32.tf32.f32 "
        "{%0,%1,%2,%3},{%4,%5,%6,%7},{%8,%9},{%0,%1,%2,%3};"
        : "+f"(c[0]), "+f"(c[1]), "+f"(c[2]), "+f"(c[3])
        : "r"(a[0]), "r"(a[1]), "r"(a[2]), "r"(a[3]), "r"(b[0]), "r"(b[1]));
}
__device__ __forceinline__ void ldsm4(unsigned* r, const unsigned* p) {
    unsigned addr = (unsigned)__cvta_generic_to_shared(p);
    asm volatile("ldmatrix.sync.aligned.m8n8.x4.shared.b16 {%0,%1,%2,%3}, [%4];"
                 : "=r"(r[0]), "=r"(r[1]), "=r"(r[2]), "=r"(r[3]) : "r"(addr));
}
__device__ __forceinline__ float4 bf4_load(const __nv_bfloat16* p) {
    uint2 u = *(const uint2*)p;
    __nv_bfloat162 a = *reinterpret_cast<const __nv_bfloat162*>(&u.x);
    __nv_bfloat162 b = *reinterpret_cast<const __nv_bfloat162*>(&u.y);
    float2 fa = __bfloat1622float2(a), fb = __bfloat1622float2(b);
    return make_float4(fa.x, fa.y, fb.x, fb.y);
}
__device__ __forceinline__ void bf4_store(__nv_bfloat16* p, float4 v) {
    __nv_bfloat162 a = __float22bfloat162_rn(make_float2(v.x, v.y));
    __nv_bfloat162 b = __float22bfloat162_rn(make_float2(v.z, v.w));
    uint2 u;
    u.x = *reinterpret_cast<unsigned*>(&a);
    u.y = *reinterpret_cast<unsigned*>(&b);
    *(uint2*)p = u;
}

// ---------------- GEMM body (R10-proven, ldmatrix) ----------------
#define AS_STR 36
#define BT_STR 36
#define GM 782   // gemm grid for M = N_NODES

__device__ void gemm_body(int bid, const float* __restrict__ A,
                          const float* __restrict__ B, float* __restrict__ C,
                          int M, int relu, int out_bf16) {
    __shared__ unsigned As[128 * AS_STR];
    __shared__ unsigned Bst[128 * BT_STR];
    int m0 = bid * 128;
    int tid = threadIdx.x;
    int lane = tid & 31, wid = tid >> 5;
    int wm = wid & 3, wn = wid >> 2;
    int gid = lane >> 2, tig = lane & 3;

    float c[2][8][4];
#pragma unroll
    for (int mt = 0; mt < 2; mt++)
#pragma unroll
        for (int nt = 0; nt < 8; nt++)
#pragma unroll
            for (int q = 0; q < 4; q++) c[mt][nt][q] = 0.f;

    int ar = tid >> 1, acb = (tid & 1) * 16;
    int bn = tid & 127, bkh = (tid >> 7) * 16;

    const unsigned* pa0 = &As[(wm * 32 + (lane & 15)) * AS_STR + ((lane >> 4) << 2)];
    const unsigned* pa1 = pa0 + 16 * AS_STR;
    const unsigned* pb  = &Bst[(wn * 64 + ((lane >> 4) << 3) + (lane & 7)) * BT_STR +
                               (((lane >> 3) & 1) << 2)];

    for (int kc = 0; kc < 128; kc += 32) {
        {
            int grow = m0 + ar;
#pragma unroll
            for (int q = 0; q < 2; q++) {
                float4 v0 = (grow < M)
                    ? *(const float4*)&A[(size_t)grow * 128 + kc + acb + q * 8]
                    : make_float4(0.f, 0.f, 0.f, 0.f);
                float4 v1 = (grow < M)
                    ? *(const float4*)&A[(size_t)grow * 128 + kc + acb + q * 8 + 4]
                    : make_float4(0.f, 0.f, 0.f, 0.f);
                *(uint4*)&As[ar * AS_STR + acb + q * 8] =
                    make_uint4(f2tf(v0.x), f2tf(v0.y), f2tf(v0.z), f2tf(v0.w));
                *(uint4*)&As[ar * AS_STR + acb + q * 8 + 4] =
                    make_uint4(f2tf(v1.x), f2tf(v1.y), f2tf(v1.z), f2tf(v1.w));
            }
#pragma unroll
            for (int q = 0; q < 4; q++) {
                int kk = bkh + q * 4;
                uint4 u;
                u.x = f2tf(B[(size_t)(kc + kk + 0) * 128 + bn]);
                u.y = f2tf(B[(size_t)(kc + kk + 1) * 128 + bn]);
                u.z = f2tf(B[(size_t)(kc + kk + 2) * 128 + bn]);
                u.w = f2tf(B[(size_t)(kc + kk + 3) * 128 + bn]);
                *(uint4*)&Bst[bn * BT_STR + kk] = u;
            }
        }
        __syncthreads();
#pragma unroll
        for (int ks = 0; ks < 4; ks++) {
            int kb = ks * 8;
            unsigned a[2][4], b[8][2];
            ldsm4(a[0], pa0 + kb);
            ldsm4(a[1], pa1 + kb);
#pragma unroll
            for (int p = 0; p < 4; p++) {
                unsigned t4[4];
                ldsm4(t4, pb + p * 16 * BT_STR + kb);
                b[2 * p][0] = t4[0]; b[2 * p][1] = t4[1];
                b[2 * p + 1][0] = t4[2]; b[2 * p + 1][1] = t4[3];
            }
#pragma unroll
            for (int mt = 0; mt < 2; mt++)
#pragma unroll
                for (int nt = 0; nt < 8; nt++) mma8(c[mt][nt], a[mt], b[nt]);
        }
        __syncthreads();
    }

    __nv_bfloat16* Cb = (__nv_bfloat16*)C;
#pragma unroll
    for (int mt = 0; mt < 2; mt++) {
        int r = m0 + wm * 32 + mt * 16 + gid;
#pragma unroll
        for (int nt = 0; nt < 8; nt++) {
            int col = wn * 64 + nt * 8 + 2 * tig;
            float2 v0 = make_float2(c[mt][nt][0], c[mt][nt][1]);
            float2 v1 = make_float2(c[mt][nt][2], c[mt][nt][3]);
            if (relu) {
                v0.x = fmaxf(v0.x, 0.f); v0.y = fmaxf(v0.y, 0.f);
                v1.x = fmaxf(v1.x, 0.f); v1.y = fmaxf(v1.y, 0.f);
            }
            if (out_bf16) {
                __nv_bfloat162 b0 = __float22bfloat162_rn(v0);
                __nv_bfloat162 b1 = __float22bfloat162_rn(v1);
                if (r < M)     *(__nv_bfloat162*)&Cb[(size_t)r * 128 + col] = b0;
                if (r + 8 < M) *(__nv_bfloat162*)&Cb[(size_t)(r + 8) * 128 + col] = b1;
            } else {
                if (r < M)     *(float2*)&C[(size_t)r * 128 + col] = v0;
                if (r + 8 < M) *(float2*)&C[(size_t)(r + 8) * 128 + col] = v1;
            }
        }
    }
}

__global__ void __launch_bounds__(256)
k_gemm_tf32(const float* __restrict__ A, const float* __restrict__ B,
            float* __restrict__ C, int M, int relu, int out_bf16) {
    gemm_body(blockIdx.x, A, B, C, M, relu, out_bf16);
}

// ---------------- fused F1: gemm_t (x@W1t -> buf1 bf16) || zero arrays -------------
#define F1_CSR 256
__global__ void __launch_bounds__(256)
k_f1(const float* __restrict__ x, const float* __restrict__ W1t) {
    if (blockIdx.x < GM) {
        gemm_body(blockIdx.x, x, W1t, g_buf1, N_NODES, 0, 1);
        return;
    }
    int stride = F1_CSR * 256;
    for (int i = (blockIdx.x - GM) * 256 + threadIdx.x; i < N_NODES; i += stride) {
        g_cnt[i] = 0;
        g_flag[i] = 0;
        g_tflag[i] = 0;
        g_istgt[i] = 0;
    }
}

// ---------------- fused F2: gemm_c (mx@W1c -> buf2 bf16) || count || istgt ---------
#define F2_CSR 512
#define F2_TGT ((T_NODES + 255) / 256)
__global__ void __launch_bounds__(256)
k_f2(const float* __restrict__ mx, const float* __restrict__ W1c,
     const int* __restrict__ dst, const int* __restrict__ tgt) {
    if (blockIdx.x < GM) {
        gemm_body(blockIdx.x, mx, W1c, g_buf2, N_NODES, 0, 1);
        return;
    }
    if (blockIdx.x < GM + F2_CSR) {
        int stride = F2_CSR * 256;
        for (int e = (blockIdx.x - GM) * 256 + threadIdx.x; e < N_EDGES; e += stride)
            atomicAdd(&g_cnt[dst[e]], 1);
        return;
    }
    int t = (blockIdx.x - GM - F2_CSR) * 256 + threadIdx.x;
    if (t < T_NODES) g_istgt[tgt[t]] = 1;
}

// ---------------- scan / prep (standalone) ----------------
__global__ void k_scan() {
    __shared__ int sums[1024];
    const int CH = (N_NODES + 1024) / 1024;
    int t = threadIdx.x;
    int base = t * CH;
    int s = 0;
    for (int i = 0; i < CH; i++) {
        int idx = base + i;
        if (idx < N_NODES) s += g_cnt[idx];
    }
    sums[t] = s;
    __syncthreads();
    for (int off = 1; off < 1024; off <<= 1) {
        int v = (t >= off) ? sums[t - off] : 0;
        __syncthreads();
        sums[t] += v;
        __syncthreads();
    }
    int run = sums[t] - s;
    for (int i = 0; i < CH; i++) {
        int idx = base + i;
        if (idx <= N_NODES) g_rowptr[idx] = run;
        if (idx < N_NODES) run += g_cnt[idx];
    }
}

__global__ void k_prep() {
    int i = blockIdx.x * blockDim.x + threadIdx.x;
    if (i < N_NODES) {
        g_cursor[i] = g_rowptr[i];
        int c = g_cnt[i];
        g_invdeg[i] = 1.0f / (float)(c > 0 ? c : 1);
    }
}

// ---------------- fused F3: fill(+tflag) || pe || wf || zb || flag -----------------
#define F3_FILL 1024
#define F3_PE   391
#define F3_WF   128
#define F3_GRID (F3_FILL + F3_PE + F3_WF + 1 + 512)
__global__ void __launch_bounds__(256)
k_f3(const int* __restrict__ src, const int* __restrict__ dst,
     const float* __restrict__ pos_enc, const float* __restrict__ Wpe,
     const float* __restrict__ W2c, const float* __restrict__ Wp1,
     const float* __restrict__ z, const float* __restrict__ bp1,
     const int* __restrict__ pair_s, const float* __restrict__ mask) {
    int b = blockIdx.x, tid = threadIdx.x;
    if (b < F3_FILL) {
        int stride = F3_FILL * 256;
        for (int e = b * 256 + tid; e < N_EDGES; e += stride) {
            int d = dst[e];
            int s = src[e];
            int pos = atomicAdd(&g_cursor[d], 1);
            g_col[pos] = s;
            if (g_istgt[d]) g_tflag[s] = 1;   // fold tflag into the edge scan
        }
    } else if (b < F3_FILL + F3_PE) {
        int n = (b - F3_FILL) * 256 + tid;
        if (n < N_NODES) {
            float4 p = *(const float4*)&pos_enc[n * 4];
#pragma unroll
            for (int i = 0; i < 4; i++) {
                g_pe[n * 4 + i] = p.x * Wpe[i * 4 + 0] + p.y * Wpe[i * 4 + 1] +
                                  p.z * Wpe[i * 4 + 2] + p.w * Wpe[i * 4 + 3];
            }
        }
    } else if (b < F3_FILL + F3_PE + F3_WF) {
        int i = b - F3_FILL - F3_PE;
        int j = tid;
        float acc = 0.f;
        for (int d = 0; d < DIM; d++)
            acc = fmaf(W2c[i * DIM + d], Wp1[d * HP + j], acc);
        g_wf[i * HP + j] = acc;
    } else if (b < F3_FILL + F3_PE + F3_WF + 1) {
        int j = tid;
        float acc = bp1[j];
        for (int i = 0; i < ZDIM; i++)
            acc = fmaf(z[i], Wp1[(128 + i) * HP + j], acc);
        g_zb[j] = acc;
    } else {
        int i = (b - F3_FILL - F3_PE - F3_WF - 1) * 256 + tid;
        if (i < P_PAIRS && mask[i] != 0.f) g_flag[pair_s[i]] = 1;
    }
}

// ---------------- agg bodies ----------------
__device__ __forceinline__ void agg_node(const float* __restrict__ in, int n, int lane,
                                         float4& r) {
    int s = g_rowptr[n], e = g_rowptr[n + 1];
    float4 a0 = make_float4(0.f, 0.f, 0.f, 0.f), a1 = a0, a2 = a0, a3 = a0;
    int i = s;
    for (; i + 4 <= e; i += 4) {
        int c0 = g_col[i], c1 = g_col[i + 1], c2 = g_col[i + 2], c3 = g_col[i + 3];
        float4 v0 = *(const float4*)&in[(size_t)c0 * 128 + lane * 4];
        float4 v1 = *(const float4*)&in[(size_t)c1 * 128 + lane * 4];
        float4 v2 = *(const float4*)&in[(size_t)c2 * 128 + lane * 4];
        float4 v3 = *(const float4*)&in[(size_t)c3 * 128 + lane * 4];
        a0.x += v0.x; a0.y += v0.y; a0.z += v0.z; a0.w += v0.w;
        a1.x += v1.x; a1.y += v1.y; a1.z += v1.z; a1.w += v1.w;
        a2.x += v2.x; a2.y += v2.y; a2.z += v2.z; a2.w += v2.w;
        a3.x += v3.x; a3.y += v3.y; a3.z += v3.z; a3.w += v3.w;
    }
    for (; i < e; i++) {
        int c = g_col[i];
        float4 v = *(const float4*)&in[(size_t)c * 128 + lane * 4];
        a0.x += v.x; a0.y += v.y; a0.z += v.z; a0.w += v.w;
    }
    float inv = g_invdeg[n];
    r.x = (a0.x + a1.x + a2.x + a3.x) * inv;
    r.y = (a0.y + a1.y + a2.y + a3.y) * inv;
    r.z = (a0.z + a1.z + a2.z + a3.z) * inv;
    r.w = (a0.w + a1.w + a2.w + a3.w) * inv;
}

__device__ __forceinline__ void agg_node_bf16(const __nv_bfloat16* __restrict__ in,
                                              int n, int lane, float4& r) {
    int s = g_rowptr[n], e = g_rowptr[n + 1];
    float4 a0 = make_float4(0.f, 0.f, 0.f, 0.f), a1 = a0, a2 = a0, a3 = a0;
    int i = s;
    for (; i + 4 <= e; i += 4) {
        int c0 = g_col[i], c1 = g_col[i + 1], c2 = g_col[i + 2], c3 = g_col[i + 3];
        float4 v0 = bf4_load(&in[(size_t)c0 * 128 + lane * 4]);
        float4 v1 = bf4_load(&in[(size_t)c1 * 128 + lane * 4]);
        float4 v2 = bf4_load(&in[(size_t)c2 * 128 + lane * 4]);
        float4 v3 = bf4_load(&in[(size_t)c3 * 128 + lane * 4]);
        a0.x += v0.x; a0.y += v0.y; a0.z += v0.z; a0.w += v0.w;
        a1.x += v1.x; a1.y += v1.y; a1.z += v1.z; a1.w += v1.w;
        a2.x += v2.x; a2.y += v2.y; a2.z += v2.z; a2.w += v2.w;
        a3.x += v3.x; a3.y += v3.y; a3.z += v3.z; a3.w += v3.w;
    }
    for (; i < e; i++) {
        int c = g_col[i];
        float4 v = bf4_load(&in[(size_t)c * 128 + lane * 4]);
        a0.x += v.x; a0.y += v.y; a0.z += v.z; a0.w += v.w;
    }
    float inv = g_invdeg[n];
    r.x = (a0.x + a1.x + a2.x + a3.x) * inv;
    r.y = (a0.y + a1.y + a2.y + a3.y) * inv;
    r.z = (a0.z + a1.z + a2.z + a3.z) * inv;
    r.w = (a0.w + a1.w + a2.w + a3.w) * inv;
}

// ---------------- fused F4: agg_b2b (h_c) || agg_tflagged (ht) ---------------------
#define AGG_GRID 12500
__global__ void __launch_bounds__(256)
k_f4() {
    int b = blockIdx.x;
    int lane = threadIdx.x & 31;
    if (b < AGG_GRID) {
        int n = b * 8 + (threadIdx.x >> 5);
        if (n >= N_NODES) return;
        float4 r;
        agg_node_bf16((const __nv_bfloat16*)g_buf2, n, lane, r);
        r.x = fmaxf(r.x, 0.f); r.y = fmaxf(r.y, 0.f);
        r.z = fmaxf(r.z, 0.f); r.w = fmaxf(r.w, 0.f);
        bf4_store(&((__nv_bfloat16*)g_buf4)[(size_t)n * 128 + lane * 4], r);
    } else {
        int n = (b - AGG_GRID) * 8 + (threadIdx.x >> 5);
        if (n >= N_NODES) return;
        if (!g_tflag[n]) return;
        float4 r;
        agg_node_bf16((const __nv_bfloat16*)g_buf1, n, lane, r);
        r.x = fmaxf(r.x, 0.f); r.y = fmaxf(r.y, 0.f);
        r.z = fmaxf(r.z, 0.f); r.w = fmaxf(r.w, 0.f);
        *(float4*)&g_buf3[(size_t)n * 128 + lane * 4] = r;
    }
}

// ---------------- fused F5: agg_flagged (m) || agg_target --------------------------
#define F5_TGT ((T_NODES + 7) / 8)
__global__ void __launch_bounds__(256)
k_f5(const int* __restrict__ tgt) {
    int b = blockIdx.x;
    int lane = threadIdx.x & 31;
    if (b < AGG_GRID) {
        int n = b * 8 + (threadIdx.x >> 5);
        if (n >= N_NODES) return;
        if (!g_flag[n]) return;
        float4 r;
        agg_node_bf16((const __nv_bfloat16*)g_buf4, n, lane, r);
        *(float4*)&g_buf1[(size_t)n * 128 + lane * 4] = r;
    } else {
        int t = (b - AGG_GRID) * 8 + (threadIdx.x >> 5);
        if (t >= T_NODES) return;
        int n = tgt[t];
        float4 r;
        agg_node(g_buf3, n, lane, r);
        *(float4*)&g_tbuf[(size_t)t * 128 + lane * 4] = r;
    }
}

// ---------------- fused predictor (tf32 MMA + ldmatrix, both layers) ---------------
#define FS_STR 140
#define WT_STR 36
#define HID_STR 260
#define PRED_SMEM_UINTS (64 * HID_STR + 128 * WT_STR)
#define PRED_SMEM (PRED_SMEM_UINTS * 4)

__global__ void __launch_bounds__(256)
k_pred(const float* __restrict__ m, const int* __restrict__ pair_s,
       const int* __restrict__ pair_t, const int* __restrict__ tgt,
       const float* __restrict__ mask, const float* __restrict__ Wp1,
       const float* __restrict__ Wp2, const float* __restrict__ bp2,
       float* __restrict__ out) {
    extern __shared__ unsigned sm[];
    int r0 = blockIdx.x * 64;
    int tid = threadIdx.x;
    __shared__ float ms[64];
    if (tid < 64) ms[tid] = mask[r0 + tid];
    int any = __syncthreads_or(tid < 64 && mask[r0 + tid] != 0.f);
    if (!any) {
        float4 zero = make_float4(0.f, 0.f, 0.f, 0.f);
#pragma unroll
        for (int i = 0; i < 8; i++) {
            int idx = tid + i * 256;
            *(float4*)&out[(size_t)r0 * 128 + idx * 4] = zero;
        }
        return;
    }

    unsigned* feats = sm;
    unsigned* wst   = sm + 64 * FS_STR;
    unsigned* hid   = sm;
    unsigned* ws2t  = sm + 64 * HID_STR;

    int lane = tid & 31, wid = tid >> 5;
    int wm = wid & 1, wn = wid >> 1;
    int gid = lane >> 2, tig = lane & 3;

    const unsigned* pfa = &feats[(wm * 32 + (lane & 15)) * FS_STR + ((lane >> 4) << 2)];
    const unsigned* pwb = &wst[(wn * 64 + ((lane >> 4) << 3) + (lane & 7)) * WT_STR +
                               (((lane >> 3) & 1) << 2)];
    const unsigned* pha = &hid[(wm * 32 + (lane & 15)) * HID_STR + ((lane >> 4) << 2)];
    const unsigned* pw2b = &ws2t[(wn * 32 + ((lane >> 4) << 3) + (lane & 7)) * WT_STR +
                                 (((lane >> 3) & 1) << 2)];

#pragma unroll
    for (int i = 0; i < 8; i++) {
        int idx = tid + i * 256;
        int r = idx >> 5, q = (idx & 31) << 2;
        int sN = pair_s[r0 + r];
        float4 v = *(const float4*)&m[(size_t)sN * 128 + q];
        uint4 u = make_uint4(f2tf(v.x), f2tf(v.y), f2tf(v.z), f2tf(v.w));
        *(uint4*)&feats[r * FS_STR + q] = u;
    }
    if (tid < 64) {
        int sN = pair_s[r0 + tid];
        int tN = tgt[pair_t[r0 + tid]];
        float4 ps = *(const float4*)&g_pe[sN * 4];
        float4 pt = *(const float4*)&g_pe[tN * 4];
        *(uint4*)&feats[tid * FS_STR + 128] =
            make_uint4(f2tf(ps.x), f2tf(ps.y), f2tf(ps.z), f2tf(ps.w));
        *(uint4*)&feats[tid * FS_STR + 132] =
            make_uint4(f2tf(pt.x), f2tf(pt.y), f2tf(pt.z), f2tf(pt.w));
    }

    float c[2][8][4];
#pragma unroll
    for (int mt = 0; mt < 2; mt++)
#pragma unroll
        for (int nt = 0; nt < 8; nt++)
#pragma unroll
            for (int q = 0; q < 4; q++) c[mt][nt][q] = 0.f;

    for (int ch = 0; ch < 5; ch++) {
        int nrows = (ch < 4) ? 32 : 8;
        {
            int n = tid;
            int nq = nrows >> 2;
#pragma unroll
            for (int q = 0; q < 8; q++) {
                if (q >= nq) break;
                int kk = q * 4;
                uint4 u;
                if (ch < 4) {
                    const float* base = &g_wf[(size_t)(ch * 32 + kk) * 256 + n];
                    u.x = f2tf(base[0]);
                    u.y = f2tf(base[256]);
                    u.z = f2tf(base[512]);
                    u.w = f2tf(base[768]);
                } else {
                    const float* base = &Wp1[(size_t)(192 + kk) * 256 + n];
                    u.x = f2tf(base[0]);
                    u.y = f2tf(base[256]);
                    u.z = f2tf(base[512]);
                    u.w = f2tf(base[768]);
                }
                *(uint4*)&wst[n * WT_STR + kk] = u;
            }
        }
        __syncthreads();
        int nks = nrows >> 3;
        for (int ks = 0; ks < nks; ks++) {
            int kb = ch * 32 + ks * 8;
            int kl = ks * 8;
            unsigned a[2][4], b[8][2];
            ldsm4(a[0], pfa + kb);
            ldsm4(a[1], pfa + 16 * FS_STR + kb);
#pragma unroll
            for (int p = 0; p < 4; p++) {
                unsigned t4[4];
                ldsm4(t4, pwb + p * 16 * WT_STR + kl);
                b[2 * p][0] = t4[0]; b[2 * p][1] = t4[1];
                b[2 * p + 1][0] = t4[2]; b[2 * p + 1][1] = t4[3];
            }
#pragma unroll
            for (int mt = 0; mt < 2; mt++)
#pragma unroll
                for (int nt = 0; nt < 8; nt++) mma8(c[mt][nt], a[mt], b[nt]);
        }
        __syncthreads();
    }

#pragma unroll
    for (int mt = 0; mt < 2; mt++) {
        int r = wm * 32 + mt * 16 + gid;
#pragma unroll
        for (int nt = 0; nt < 8; nt++) {
            int col = wn * 64 + nt * 8 + 2 * tig;
            float2 zbv = *(const float2*)&g_zb[col];
            uint2 u0 = make_uint2(f2tf(fmaxf(c[mt][nt][0] + zbv.x, 0.f)),
                                  f2tf(fmaxf(c[mt][nt][1] + zbv.y, 0.f)));
            uint2 u1 = make_uint2(f2tf(fmaxf(c[mt][nt][2] + zbv.x, 0.f)),
                                  f2tf(fmaxf(c[mt][nt][3] + zbv.y, 0.f)));
            *(uint2*)&hid[r * HID_STR + col] = u0;
            *(uint2*)&hid[(r + 8) * HID_STR + col] = u1;
        }
    }
    __syncthreads();

    float c2[2][4][4];
#pragma unroll
    for (int mt = 0; mt < 2; mt++)
#pragma unroll
        for (int nt = 0; nt < 4; nt++)
#pragma unroll
            for (int q = 0; q < 4; q++) c2[mt][nt][q] = 0.f;

    int w2n = tid & 127, w2kh = (tid >> 7) * 16;
    for (int ch = 0; ch < 8; ch++) {
        {
#pragma unroll
            for (int q = 0; q < 4; q++) {
                int kk = w2kh + q * 4;
                const float* base = &Wp2[(size_t)(ch * 32 + kk) * 128 + w2n];
                uint4 u;
                u.x = f2tf(base[0]);
                u.y = f2tf(base[128]);
                u.z = f2tf(base[256]);
                u.w = f2tf(base[384]);
                *(uint4*)&ws2t[w2n * WT_STR + kk] = u;
            }
        }
        __syncthreads();
#pragma unroll
        for (int ks = 0; ks < 4; ks++) {
            int kb = ch * 32 + ks * 8;
            int kl = ks * 8;
            unsigned a[2][4], b[4][2];
            ldsm4(a[0], pha + kb);
            ldsm4(a[1], pha + 16 * HID_STR + kb);
#pragma unroll
            for (int p = 0; p < 2; p++) {
                unsigned t4[4];
                ldsm4(t4, pw2b + p * 16 * WT_STR + kl);
                b[2 * p][0] = t4[0]; b[2 * p][1] = t4[1];
                b[2 * p + 1][0] = t4[2]; b[2 * p + 1][1] = t4[3];
            }
#pragma unroll
            for (int mt = 0; mt < 2; mt++)
#pragma unroll
                for (int nt = 0; nt < 4; nt++) mma8(c2[mt][nt], a[mt], b[nt]);
        }
        __syncthreads();
    }

#pragma unroll
    for (int mt = 0; mt < 2; mt++) {
        int lr = wm * 32 + mt * 16 + gid;
        float m0v = ms[lr], m1v = ms[lr + 8];
#pragma unroll
        for (int nt = 0; nt < 4; nt++) {
            int col = wn * 32 + nt * 8 + 2 * tig;
            float2 bb = *(const float2*)&bp2[col];
            float2 v0 = make_float2((c2[mt][nt][0] + bb.x) * m0v,
                                    (c2[mt][nt][1] + bb.y) * m0v);
            float2 v1 = make_float2((c2[mt][nt][2] + bb.x) * m1v,
                                    (c2[mt][nt][3] + bb.y) * m1v);
            *(float2*)&out[(size_t)(r0 + lr) * 128 + col] = v0;
            *(float2*)&out[(size_t)(r0 + lr + 8) * 128 + col] = v1;
        }
    }
}

// ---------------- launch ----------------
extern "C" void kernel_launch(void* const* d_in, const int* in_sizes, int n_in,
                              void* d_out, int out_size) {
    const float* x            = (const float*)d_in[0];
    const float* masked_x     = (const float*)d_in[1];
    const float* pos_enc      = (const float*)d_in[2];
    const int*   edge_src     = (const int*)d_in[3];
    const int*   edge_dst     = (const int*)d_in[4];
    const int*   target_nodes = (const int*)d_in[5];
    const int*   pair_t       = (const int*)d_in[6];
    const int*   pair_s       = (const int*)d_in[7];
    const float* pair_mask    = (const float*)d_in[8];
    const float* W1t          = (const float*)d_in[9];
    const float* W2t          = (const float*)d_in[10];
    const float* W1c          = (const float*)d_in[11];
    const float* W2c          = (const float*)d_in[12];
    const float* Wpe          = (const float*)d_in[13];
    const float* z            = (const float*)d_in[14];
    const float* Wp1          = (const float*)d_in[15];
    const float* bp1          = (const float*)d_in[16];
    const float* Wp2          = (const float*)d_in[17];
    const float* bp2          = (const float*)d_in[18];
    float* out = (float*)d_out;

    float *buf1, *tbuf;
    cudaGetSymbolAddress((void**)&buf1, g_buf1);
    cudaGetSymbolAddress((void**)&tbuf, g_tbuf);

    cudaFuncSetAttribute(k_pred, cudaFuncAttributeMaxDynamicSharedMemorySize,
                         PRED_SMEM);

    const int TPB = 256;

    // F1: gemm_t || zero(cnt/flag/tflag/istgt)
    k_f1<<<GM + F1_CSR, TPB>>>(x, W1t);
    // F2: gemm_c || count || istgt set
    k_f2<<<GM + F2_CSR + F2_TGT, TPB>>>(masked_x, W1c, edge_dst, target_nodes);
    // scan + prep
    k_scan<<<1, 1024>>>();
    k_prep<<<(N_NODES + TPB - 1) / TPB, TPB>>>();
    // F3: fill(+tflag) || pe || wf || zb || flag
    k_f3<<<F3_GRID, TPB>>>(edge_src, edge_dst, pos_enc, Wpe, W2c, Wp1, z, bp1,
                           pair_s, pair_mask);
    // F4: h_c agg || ht agg
    k_f4<<<AGG_GRID * 2, TPB>>>();
    // F5: m agg || target agg
    k_f5<<<AGG_GRID + F5_TGT, TPB>>>(target_nodes);
    // target tail: tiny GEMM straight into output embeddings
    k_gemm_tf32<<<T_NODES / 128, TPB>>>(tbuf, W2t, out + (size_t)P_PAIRS * DOUT,
                                        T_NODES, 0, 0);
    // fused predictor MLP
    k_pred<<<P_PAIRS / 64, TPB, PRED_SMEM>>>(buf1, pair_s, pair_t, target_nodes,
                                             pair_mask, Wp1, Wp2, bp2, out);
}